// round 12
// baseline (speedup 1.0000x reference)
#include <cuda_runtime.h>
#include <cuda_fp16.h>
#include <cstdint>

// ---------------------------------------------------------------------------
// ExtendedGCN: 3-layer GCN (PyG GCNConv) + softmax.
//   Pull-based aggregation over per-call CSR-by-dst, packed (src, norm);
//   CSR filled via cursor atomics.  Single fused single-block scan kernel
//   (offs/cursor/dinv + deg self-zeroing -> no memset, no scan3).
//   Layers 1/2 GEMM: tensor cores, split-tf32 (fp32 accuracy), fp16 outputs.
//   Layer-3 GEMV (64x16) fused into agg2 epilogue via warp shuffles.
//   relu fused into agg1; softmax fused into agg3.
//   CSR build overlapped with layer-1 GEMM on a second stream.
// edge_index is int32 on device (JAX x64 disabled).
// g_deg invariant: zero at call entry (BSS zero-init + scan re-zeroes).
// ---------------------------------------------------------------------------

#define NMAX 50000
#define EMAX 800000

__device__ __half g_H16[(size_t)NMAX * 128];  // fp16 GEMM outputs (layers 1/2)
__device__ __half g_A16[(size_t)NMAX * 128];  // fp16 agg1 output (GEMM2 input)
__device__ float  g_H3[(size_t)NMAX * 16];    // fp32 layer-3 logits (pre-agg)
__device__ float  g_dinv[NMAX];
__device__ int    g_deg[NMAX];                // ZERO at entry, re-zeroed by scan
__device__ int    g_offs[NMAX + 1];           // GLOBAL exclusive offsets
__device__ int    g_cursor[NMAX];
__device__ float2 g_csr[EMAX];                // (src as int bits, norm)

// ----------------------------- CSR build ----------------------------------

__global__ void deg_kernel(const int* __restrict__ dst, int E) {
    int e = blockIdx.x * blockDim.x + threadIdx.x;
    if (e < E) atomicAdd(&g_deg[dst[e]], 1);
}

// ONE block, 1024 threads: full exclusive scan of deg over n elements,
// tile-by-tile (1024/tile) with next-tile prefetch. Also writes cursor,
// dinv, and re-zeroes deg (self-cleaning for the next call/replay).
__global__ void scan_all_kernel(int n, int E) {
    __shared__ int warp_tot[32];
    __shared__ int tile_tot;
    const int tid = threadIdx.x;
    const int lane = tid & 31;
    const int warp = tid >> 5;
    const int nt = (n + 1023) >> 10;

    int running = 0;
    int idx = tid;
    int v_next = (idx < n) ? g_deg[idx] : 0;

    for (int t = 0; t < nt; t++) {
        int v = v_next;
        int idx_next = idx + 1024;
        if (t + 1 < nt) v_next = (idx_next < n) ? g_deg[idx_next] : 0;

        // block-exclusive scan of v
        int inc = v;
#pragma unroll
        for (int o = 1; o < 32; o <<= 1) {
            int x = __shfl_up_sync(0xFFFFFFFFu, inc, o);
            if (lane >= o) inc += x;
        }
        if (lane == 31) warp_tot[warp] = inc;
        __syncthreads();
        if (warp == 0) {
            int w = warp_tot[lane];
            int wi = w;
#pragma unroll
            for (int o = 1; o < 32; o <<= 1) {
                int x = __shfl_up_sync(0xFFFFFFFFu, wi, o);
                if (lane >= o) wi += x;
            }
            warp_tot[lane] = wi - w;          // exclusive warp prefix
            if (lane == 31) tile_tot = wi;    // tile total
        }
        __syncthreads();

        int excl = inc - v + warp_tot[warp] + running;
        if (idx < n) {
            g_offs[idx] = excl;
            g_cursor[idx] = excl;
            g_dinv[idx] = rsqrtf((float)(v + 1));
            g_deg[idx] = 0;                   // self-clean for next call
        }
        running += tile_tot;
        __syncthreads();                      // protect warp_tot/tile_tot reuse
        idx = idx_next;
    }
    if (tid == 0) g_offs[n] = E;
}

__global__ void scatter_kernel(const int* __restrict__ src,
                               const int* __restrict__ dst, int E) {
    int e = blockIdx.x * blockDim.x + threadIdx.x;
    if (e < E) {
        int s = src[e], d = dst[e];
        int pos = atomicAdd(&g_cursor[d], 1);
        float nrm = g_dinv[s] * g_dinv[d];
        g_csr[pos] = make_float2(__int_as_float(s), nrm);
    }
}

// ------------------------- tf32 tensor GEMM --------------------------------

__device__ __forceinline__ uint32_t f2tf32(float x) {
    uint32_t r;
    asm("cvt.rna.tf32.f32 %0, %1;" : "=r"(r) : "f"(x));
    return r;
}

__device__ __forceinline__ void mma_tf32(float* c, const uint32_t* a,
                                         uint32_t b0, uint32_t b1) {
    asm volatile(
        "mma.sync.aligned.m16n8k8.row.col.f32.tf32.tf32.f32 "
        "{%0,%1,%2,%3}, {%4,%5,%6,%7}, {%8,%9}, {%0,%1,%2,%3};\n"
        : "+f"(c[0]), "+f"(c[1]), "+f"(c[2]), "+f"(c[3])
        : "r"(a[0]), "r"(a[1]), "r"(a[2]), "r"(a[3]), "r"(b0), "r"(b1));
}

// A: fp32 or fp16 in, W fp32 in, C fp16 out.
template <int BN, typename AT>
__global__ void gemm_tf32_kernel(const AT* __restrict__ A,
                                 const float* __restrict__ W,
                                 __half* __restrict__ C, int M, int K, int N) {
    constexpr int BM = 128, BK = 16, THREADS = 256;
    constexpr int AS = BK + 4;
    constexpr int WS = BN + 4;
    constexpr int NF = BN / 16;
    constexpr bool A_HALF = (sizeof(AT) == 2);

    __shared__ float As[2][BM * AS];
    __shared__ float Ws[2][BK * WS];

    const int tid = threadIdx.x;
    const int lane = tid & 31;
    const int warp = tid >> 5;
    const int g = lane >> 2;
    const int tg = lane & 3;
    const int wrb = (warp & 3) * 32;
    const int wcb = (warp >> 2) * (BN / 2);
    const int brow = blockIdx.y * BM;
    const int bcol = blockIdx.x * BN;

    float c[2][NF][4];
#pragma unroll
    for (int mi = 0; mi < 2; mi++)
#pragma unroll
        for (int ni = 0; ni < NF; ni++)
#pragma unroll
            for (int j = 0; j < 4; j++) c[mi][ni][j] = 0.0f;

    for (int k0 = 0; k0 < K; k0 += BK) {
#pragma unroll
        for (int p = tid; p < BM * BK / 4; p += THREADS) {
            int r = p / (BK / 4);
            int cc = (p % (BK / 4)) * 4;
            int gr = brow + r;
            float vv[4] = {0.f, 0.f, 0.f, 0.f};
            if (gr < M) {
                if (A_HALF) {
                    uint2 hv = *(const uint2*)&A[(size_t)gr * K + k0 + cc];
                    float2 f01 = __half22float2(*(__half2*)&hv.x);
                    float2 f23 = __half22float2(*(__half2*)&hv.y);
                    vv[0] = f01.x; vv[1] = f01.y; vv[2] = f23.x; vv[3] = f23.y;
                } else {
                    float4 v = *(const float4*)&A[(size_t)gr * K + k0 + cc];
                    vv[0] = v.x; vv[1] = v.y; vv[2] = v.z; vv[3] = v.w;
                }
            }
#pragma unroll
            for (int j = 0; j < 4; j++) {
                uint32_t big = f2tf32(vv[j]);
                float res = vv[j] - __uint_as_float(big);
                As[0][r * AS + cc + j] = __uint_as_float(big);
                As[1][r * AS + cc + j] = __uint_as_float(f2tf32(res));
            }
        }
#pragma unroll
        for (int p = tid; p < BK * BN / 4; p += THREADS) {
            int r = p / (BN / 4);
            int cc = (p % (BN / 4)) * 4;
            float4 v = *(const float4*)&W[(size_t)(k0 + r) * N + bcol + cc];
            const float vv[4] = {v.x, v.y, v.z, v.w};
#pragma unroll
            for (int j = 0; j < 4; j++) {
                uint32_t big = f2tf32(vv[j]);
                float res = vv[j] - __uint_as_float(big);
                Ws[0][r * WS + cc + j] = __uint_as_float(big);
                Ws[1][r * WS + cc + j] = __uint_as_float(f2tf32(res));
            }
        }
        __syncthreads();

#pragma unroll
        for (int ks = 0; ks < BK / 8; ks++) {
            const int kb = ks * 8;
            uint32_t Ab[2][4], Ar[2][4];
#pragma unroll
            for (int mi = 0; mi < 2; mi++) {
                int r0 = wrb + mi * 16 + g;
                Ab[mi][0] = __float_as_uint(As[0][r0 * AS + kb + tg]);
                Ab[mi][1] = __float_as_uint(As[0][(r0 + 8) * AS + kb + tg]);
                Ab[mi][2] = __float_as_uint(As[0][r0 * AS + kb + tg + 4]);
                Ab[mi][3] = __float_as_uint(As[0][(r0 + 8) * AS + kb + tg + 4]);
                Ar[mi][0] = __float_as_uint(As[1][r0 * AS + kb + tg]);
                Ar[mi][1] = __float_as_uint(As[1][(r0 + 8) * AS + kb + tg]);
                Ar[mi][2] = __float_as_uint(As[1][r0 * AS + kb + tg + 4]);
                Ar[mi][3] = __float_as_uint(As[1][(r0 + 8) * AS + kb + tg + 4]);
            }
#pragma unroll
            for (int ni = 0; ni < NF; ni++) {
                int col = wcb + ni * 8 + g;
                uint32_t Bb0 = __float_as_uint(Ws[0][(kb + tg) * WS + col]);
                uint32_t Bb1 = __float_as_uint(Ws[0][(kb + tg + 4) * WS + col]);
                uint32_t Br0 = __float_as_uint(Ws[1][(kb + tg) * WS + col]);
                uint32_t Br1 = __float_as_uint(Ws[1][(kb + tg + 4) * WS + col]);
#pragma unroll
                for (int mi = 0; mi < 2; mi++) {
                    mma_tf32(c[mi][ni], Ab[mi], Bb0, Bb1);
                    mma_tf32(c[mi][ni], Ar[mi], Bb0, Bb1);
                    mma_tf32(c[mi][ni], Ab[mi], Br0, Br1);
                }
            }
        }
        __syncthreads();
    }

#pragma unroll
    for (int mi = 0; mi < 2; mi++) {
        int gr0 = brow + wrb + mi * 16 + g;
        int gr1 = gr0 + 8;
#pragma unroll
        for (int ni = 0; ni < NF; ni++) {
            int gc = bcol + wcb + ni * 8 + 2 * tg;
            if (gr0 < M)
                *(__half2*)&C[(size_t)gr0 * N + gc] =
                    __floats2half2_rn(c[mi][ni][0], c[mi][ni][1]);
            if (gr1 < M)
                *(__half2*)&C[(size_t)gr1 * N + gc] =
                    __floats2half2_rn(c[mi][ni][2], c[mi][ni][3]);
        }
    }
}

// ---------------- agg1: fp16 gather, relu, fp16 out (D=128) ----------------

__global__ void agg1_kernel(__half* __restrict__ out,
                            const __half* __restrict__ H,
                            const float* __restrict__ b, int n) {
    constexpr int D = 128;
    int warp = (blockIdx.x * blockDim.x + threadIdx.x) >> 5;
    int f = threadIdx.x & 31;
    int i = warp;                      // 1 node per warp
    if (i >= n) return;

    float di = g_dinv[i];
    float s2 = di * di;
    uint2 hp = *(const uint2*)&H[(size_t)i * D + 4 * f];
    float2 h01 = __half22float2(*(__half2*)&hp.x);
    float2 h23 = __half22float2(*(__half2*)&hp.y);
    float4 bb = ((const float4*)b)[f];
    float4 acc;
    acc.x = bb.x + s2 * h01.x;
    acc.y = bb.y + s2 * h01.y;
    acc.z = bb.z + s2 * h23.x;
    acc.w = bb.w + s2 * h23.y;

    int beg = g_offs[i], end = g_offs[i + 1];
#pragma unroll 8
    for (int e = beg; e < end; e++) {
        float2 p = __ldg(&g_csr[e]);
        int s = __float_as_int(p.x);
        float nrm = p.y;
        uint2 vp = *(const uint2*)&H[(size_t)s * D + 4 * f];
        float2 v01 = __half22float2(*(__half2*)&vp.x);
        float2 v23 = __half22float2(*(__half2*)&vp.y);
        acc.x += nrm * v01.x;
        acc.y += nrm * v01.y;
        acc.z += nrm * v23.x;
        acc.w += nrm * v23.y;
    }

    acc.x = fmaxf(acc.x, 0.0f);
    acc.y = fmaxf(acc.y, 0.0f);
    acc.z = fmaxf(acc.z, 0.0f);
    acc.w = fmaxf(acc.w, 0.0f);

    uint2 o;
    *(__half2*)&o.x = __floats2half2_rn(acc.x, acc.y);
    *(__half2*)&o.y = __floats2half2_rn(acc.z, acc.w);
    *(uint2*)&out[(size_t)i * D + 4 * f] = o;
}

// ------- agg2 + fused 64x16 GEMV: h2 = agg(H2)+b2; logits = h2 @ W3 --------

__global__ void agg2_gemv_kernel(float* __restrict__ outH3,   // n x 16
                                 const __half* __restrict__ H,
                                 const float* __restrict__ b2,
                                 const float* __restrict__ W3, int n) {
    __shared__ __align__(16) float W3s[64 * 16];
    {
        int t = threadIdx.x;
        if (t < 256) ((float4*)W3s)[t] = ((const float4*)W3)[t];
    }
    __syncthreads();

    constexpr int D = 64, LPN = 16, NPW = 2;
    int warp = (blockIdx.x * blockDim.x + threadIdx.x) >> 5;
    int lane = threadIdx.x & 31;
    int grp = lane >> 4;
    int f = lane & 15;
    int i = warp * NPW + grp;
    if (i >= n) return;

    float di = g_dinv[i];
    float s2 = di * di;
    uint2 hp = *(const uint2*)&H[(size_t)i * D + 4 * f];
    float2 h01 = __half22float2(*(__half2*)&hp.x);
    float2 h23 = __half22float2(*(__half2*)&hp.y);
    float4 bb = ((const float4*)b2)[f];
    float4 acc;
    acc.x = bb.x + s2 * h01.x;
    acc.y = bb.y + s2 * h01.y;
    acc.z = bb.z + s2 * h23.x;
    acc.w = bb.w + s2 * h23.y;

    int beg = g_offs[i], end = g_offs[i + 1];
#pragma unroll 4
    for (int e = beg; e < end; e++) {
        float2 p = __ldg(&g_csr[e]);
        int s = __float_as_int(p.x);
        float nrm = p.y;
        uint2 vp = *(const uint2*)&H[(size_t)s * D + 4 * f];
        float2 v01 = __half22float2(*(__half2*)&vp.x);
        float2 v23 = __half22float2(*(__half2*)&vp.y);
        acc.x += nrm * v01.x;
        acc.y += nrm * v01.y;
        acc.z += nrm * v23.x;
        acc.w += nrm * v23.y;
    }

    // GEMV: logit[f] = sum_j sum_k h2[4j+k] * W3[4j+k][f]
    float part = 0.0f;
#pragma unroll
    for (int j = 0; j < LPN; j++) {
        float ax = __shfl_sync(0xFFFFFFFFu, acc.x, j, 16);
        float ay = __shfl_sync(0xFFFFFFFFu, acc.y, j, 16);
        float az = __shfl_sync(0xFFFFFFFFu, acc.z, j, 16);
        float aw = __shfl_sync(0xFFFFFFFFu, acc.w, j, 16);
        part += ax * W3s[(4 * j + 0) * 16 + f];
        part += ay * W3s[(4 * j + 1) * 16 + f];
        part += az * W3s[(4 * j + 2) * 16 + f];
        part += aw * W3s[(4 * j + 3) * 16 + f];
    }
    outH3[(size_t)i * 16 + f] = part;
}

// ---------------- agg3: fp32 gather over logits + softmax (D=16) -----------

__global__ void agg3_kernel(float* __restrict__ out,
                            const float* __restrict__ H,
                            const float* __restrict__ b, int n) {
    constexpr int LPN = 4, NPW = 8;
    int warp = (blockIdx.x * blockDim.x + threadIdx.x) >> 5;
    int lane = threadIdx.x & 31;
    int grp = lane / LPN;
    int f = lane % LPN;
    int i = warp * NPW + grp;
    if (i >= n) return;

    float di = g_dinv[i];
    float s2 = di * di;
    float4 h = ((const float4*)H)[(size_t)i * LPN + f];
    float4 bb = ((const float4*)b)[f];
    float4 acc;
    acc.x = bb.x + s2 * h.x;
    acc.y = bb.y + s2 * h.y;
    acc.z = bb.z + s2 * h.z;
    acc.w = bb.w + s2 * h.w;

    int beg = g_offs[i], end = g_offs[i + 1];
#pragma unroll 4
    for (int e = beg; e < end; e++) {
        float2 p = __ldg(&g_csr[e]);
        int s = __float_as_int(p.x);
        float nrm = p.y;
        float4 v = ((const float4*)H)[(size_t)s * LPN + f];
        acc.x += nrm * v.x;
        acc.y += nrm * v.y;
        acc.z += nrm * v.z;
        acc.w += nrm * v.w;
    }

    float m = fmaxf(fmaxf(acc.x, acc.y), fmaxf(acc.z, acc.w));
#pragma unroll
    for (int o = 1; o < LPN; o <<= 1)
        m = fmaxf(m, __shfl_xor_sync(0xFFFFFFFFu, m, o, LPN));
    acc.x = __expf(acc.x - m);
    acc.y = __expf(acc.y - m);
    acc.z = __expf(acc.z - m);
    acc.w = __expf(acc.w - m);
    float s = acc.x + acc.y + acc.z + acc.w;
#pragma unroll
    for (int o = 1; o < LPN; o <<= 1)
        s += __shfl_xor_sync(0xFFFFFFFFu, s, o, LPN);
    float inv = 1.0f / s;
    acc.x *= inv;
    acc.y *= inv;
    acc.z *= inv;
    acc.w *= inv;

    ((float4*)out)[(size_t)i * LPN + f] = acc;
}

// ------------------------------- launch -----------------------------------

static cudaStream_t s_gemm = nullptr;
static cudaEvent_t  s_evFork = nullptr, s_evJoin = nullptr;

extern "C" void kernel_launch(void* const* d_in, const int* in_sizes, int n_in,
                              void* d_out, int out_size) {
    const float* x  = (const float*)d_in[0];
    const int*   ei = (const int*)d_in[1];   // int32 (JAX x64 disabled)
    const float* W1 = (const float*)d_in[2];
    const float* b1 = (const float*)d_in[3];
    const float* W2 = (const float*)d_in[4];
    const float* b2 = (const float*)d_in[5];
    const float* W3 = (const float*)d_in[6];
    const float* b3 = (const float*)d_in[7];

    const int n = in_sizes[0] / 128;
    const int E = in_sizes[1] / 2;
    const int* src = ei;
    const int* dst = ei + E;

    float* H3;
    __half *H16, *A16;
    cudaGetSymbolAddress((void**)&H16, g_H16);
    cudaGetSymbolAddress((void**)&A16, g_A16);
    cudaGetSymbolAddress((void**)&H3, g_H3);

    if (s_gemm == nullptr) {
        cudaStreamCreateWithFlags(&s_gemm, cudaStreamNonBlocking);
        cudaEventCreateWithFlags(&s_evFork, cudaEventDisableTiming);
        cudaEventCreateWithFlags(&s_evJoin, cudaEventDisableTiming);
    }

    const int T = 256;
    auto blocks = [&](long long work) { return (int)((work + T - 1) / T); };
    const int gy = (n + 127) / 128;

    // Fork: layer-1 GEMM (independent of CSR) on side stream.
    cudaEventRecord(s_evFork, 0);
    cudaStreamWaitEvent(s_gemm, s_evFork, 0);
    gemm_tf32_kernel<128, float>
        <<<dim3(1, gy), 256, 0, s_gemm>>>(x, W1, H16, n, 128, 128);
    cudaEventRecord(s_evJoin, s_gemm);

    // CSR build on main stream (concurrent with GEMM1).
    // g_deg is zero at entry (zero-init + scan_all re-zeroes each call).
    deg_kernel<<<blocks(E), T>>>(dst, E);
    scan_all_kernel<<<1, 1024>>>(n, E);
    scatter_kernel<<<blocks(E), T>>>(src, dst, E);

    // Join: agg1 needs both CSR and H.
    cudaStreamWaitEvent(0, s_evJoin, 0);

    // ----- layer 1 aggregation (fp16 in/out, relu fused) -----
    agg1_kernel<<<blocks((long long)n * 32), T>>>(A16, H16, b1, n);

    // ----- layer 2: 128 -> 64 (tf32 TC, fp16 in -> fp16 H) -----
    gemm_tf32_kernel<64, __half>
        <<<dim3(1, gy), 256>>>(A16, W2, H16, n, 128, 64);

    // ----- layer 2 agg + fused layer-3 GEMV -> logits -----
    agg2_gemv_kernel<<<blocks((long long)n * 16), T>>>(H3, H16, b2, W3, n);

    // ----- layer 3 aggregation + softmax -> d_out -----
    agg3_kernel<<<blocks((long long)n * 4), T>>>((float*)d_out, H3, b3, n);
}

// round 13
// speedup vs baseline: 1.0337x; 1.0337x over previous
#include <cuda_runtime.h>
#include <cuda_fp16.h>
#include <cstdint>

// ---------------------------------------------------------------------------
// ExtendedGCN: 3-layer GCN (PyG GCNConv) + softmax.
//   ONE cooperative prep kernel (hist -> scan -> offs/cursor/dinv -> scatter)
//   with software grid barriers (128 co-resident blocks).
//   Pull-based aggregation over CSR-by-dst, packed (src, norm) payload.
//   Layers 1/2 GEMM: tensor cores, split-tf32 (fp32 accuracy), fp16 outputs.
//   Layer-3 GEMV (64x16) fused into agg2 epilogue; relu in agg1; softmax in agg3.
//   Prep overlapped with layer-1 GEMM on a second stream.
// edge_index is int32 on device (JAX x64 disabled).
// g_deg invariant: zero at call entry (BSS zero-init + prep re-zeroes).
// ---------------------------------------------------------------------------

#define NMAX 50000
#define EMAX 800000
#define PREP_BLOCKS 128
#define PREP_THREADS 1024
#define NT ((NMAX + 1023) >> 10)   // 49 scan tiles

__device__ __half g_H16[(size_t)NMAX * 128];  // fp16 GEMM outputs (layers 1/2)
__device__ __half g_A16[(size_t)NMAX * 128];  // fp16 agg1 output (GEMM2 input)
__device__ float  g_H3[(size_t)NMAX * 16];    // fp32 layer-3 logits (pre-agg)
__device__ float  g_dinv[NMAX];
__device__ int    g_deg[NMAX];                // zero at entry, re-zeroed by prep
__device__ int    g_offs[NMAX + 1];           // GLOBAL exclusive offsets
__device__ int    g_cursor[NMAX];
__device__ float2 g_csr[EMAX];                // (src as int bits, norm)
__device__ int    g_bsum[NT];

// -------- software grid barrier (sense-reversing; replay-safe state) -------

__device__ volatile unsigned g_bar_gen = 0;
__device__ unsigned g_bar_cnt = 0;

__device__ __forceinline__ void grid_barrier() {
    __syncthreads();
    if (threadIdx.x == 0) {
        __threadfence();                      // publish this block's writes
        unsigned my = g_bar_gen;
        if (atomicAdd(&g_bar_cnt, 1) == gridDim.x - 1) {
            atomicExch(&g_bar_cnt, 0);        // reset BEFORE releasing
            __threadfence();
            g_bar_gen = my + 1;               // release
        } else {
            while (g_bar_gen == my) {}
        }
    }
    __syncthreads();
}

// -------------------- fused CSR-build (one kernel) -------------------------

__global__ void __launch_bounds__(PREP_THREADS, 1)
prep_kernel(const int* __restrict__ src, const int* __restrict__ dst,
            int n, int E) {
    __shared__ int warp_tot[32];
    const int tid = threadIdx.x;
    const int lane = tid & 31;
    const int warp = tid >> 5;
    const int bid = blockIdx.x;
    const int gstride = gridDim.x * PREP_THREADS;
    const int gtid = bid * PREP_THREADS + tid;

    // ---- phase 1: degree histogram (grid-stride) ----
    for (int e = gtid; e < E; e += gstride)
        atomicAdd(&g_deg[dst[e]], 1);
    grid_barrier();

    // ---- phase 2: per-tile exclusive scan (blocks 0..NT-1) ----
    int excl = 0, v = 0, idx = -1;
    const int nt = (n + 1023) >> 10;
    if (bid < nt) {
        idx = (bid << 10) + tid;
        v = (idx < n) ? g_deg[idx] : 0;
        int inc = v;
#pragma unroll
        for (int o = 1; o < 32; o <<= 1) {
            int x = __shfl_up_sync(0xFFFFFFFFu, inc, o);
            if (lane >= o) inc += x;
        }
        if (lane == 31) warp_tot[warp] = inc;
        __syncthreads();
        if (warp == 0) {
            int w = warp_tot[lane];
            int wi = w;
#pragma unroll
            for (int o = 1; o < 32; o <<= 1) {
                int x = __shfl_up_sync(0xFFFFFFFFu, wi, o);
                if (lane >= o) wi += x;
            }
            warp_tot[lane] = wi - w;
            if (lane == 31) g_bsum[bid] = wi;
        }
        __syncthreads();
        excl = inc - v + warp_tot[warp];
    }
    grid_barrier();

    // ---- phase 3: add cross-tile prefix; write offs/cursor/dinv; zero deg --
    if (bid < nt && idx < n) {
        int pre = 0;
        for (int j = 0; j < bid; j++) pre += g_bsum[j];   // L1 broadcast hits
        int o = excl + pre;
        g_offs[idx] = o;
        g_cursor[idx] = o;
        g_dinv[idx] = rsqrtf((float)(v + 1));
        g_deg[idx] = 0;                                   // self-clean
    }
    if (gtid == 0) g_offs[n] = E;
    grid_barrier();

    // ---- phase 4: CSR fill (grid-stride, cursor atomics) ----
    for (int e = gtid; e < E; e += gstride) {
        int s = src[e], d = dst[e];
        int pos = atomicAdd(&g_cursor[d], 1);
        float nrm = g_dinv[s] * g_dinv[d];
        g_csr[pos] = make_float2(__int_as_float(s), nrm);
    }
}

// ------------------------- tf32 tensor GEMM --------------------------------

__device__ __forceinline__ uint32_t f2tf32(float x) {
    uint32_t r;
    asm("cvt.rna.tf32.f32 %0, %1;" : "=r"(r) : "f"(x));
    return r;
}

__device__ __forceinline__ void mma_tf32(float* c, const uint32_t* a,
                                         uint32_t b0, uint32_t b1) {
    asm volatile(
        "mma.sync.aligned.m16n8k8.row.col.f32.tf32.tf32.f32 "
        "{%0,%1,%2,%3}, {%4,%5,%6,%7}, {%8,%9}, {%0,%1,%2,%3};\n"
        : "+f"(c[0]), "+f"(c[1]), "+f"(c[2]), "+f"(c[3])
        : "r"(a[0]), "r"(a[1]), "r"(a[2]), "r"(a[3]), "r"(b0), "r"(b1));
}

// A: fp32 or fp16 in, W fp32 in, C fp16 out.
template <int BN, typename AT>
__global__ void gemm_tf32_kernel(const AT* __restrict__ A,
                                 const float* __restrict__ W,
                                 __half* __restrict__ C, int M, int K, int N) {
    constexpr int BM = 128, BK = 16, THREADS = 256;
    constexpr int AS = BK + 4;
    constexpr int WS = BN + 4;
    constexpr int NF = BN / 16;
    constexpr bool A_HALF = (sizeof(AT) == 2);

    __shared__ float As[2][BM * AS];
    __shared__ float Ws[2][BK * WS];

    const int tid = threadIdx.x;
    const int lane = tid & 31;
    const int warp = tid >> 5;
    const int g = lane >> 2;
    const int tg = lane & 3;
    const int wrb = (warp & 3) * 32;
    const int wcb = (warp >> 2) * (BN / 2);
    const int brow = blockIdx.y * BM;
    const int bcol = blockIdx.x * BN;

    float c[2][NF][4];
#pragma unroll
    for (int mi = 0; mi < 2; mi++)
#pragma unroll
        for (int ni = 0; ni < NF; ni++)
#pragma unroll
            for (int j = 0; j < 4; j++) c[mi][ni][j] = 0.0f;

    for (int k0 = 0; k0 < K; k0 += BK) {
#pragma unroll
        for (int p = tid; p < BM * BK / 4; p += THREADS) {
            int r = p / (BK / 4);
            int cc = (p % (BK / 4)) * 4;
            int gr = brow + r;
            float vv[4] = {0.f, 0.f, 0.f, 0.f};
            if (gr < M) {
                if (A_HALF) {
                    uint2 hv = *(const uint2*)&A[(size_t)gr * K + k0 + cc];
                    float2 f01 = __half22float2(*(__half2*)&hv.x);
                    float2 f23 = __half22float2(*(__half2*)&hv.y);
                    vv[0] = f01.x; vv[1] = f01.y; vv[2] = f23.x; vv[3] = f23.y;
                } else {
                    float4 v = *(const float4*)&A[(size_t)gr * K + k0 + cc];
                    vv[0] = v.x; vv[1] = v.y; vv[2] = v.z; vv[3] = v.w;
                }
            }
#pragma unroll
            for (int j = 0; j < 4; j++) {
                uint32_t big = f2tf32(vv[j]);
                float res = vv[j] - __uint_as_float(big);
                As[0][r * AS + cc + j] = __uint_as_float(big);
                As[1][r * AS + cc + j] = __uint_as_float(f2tf32(res));
            }
        }
#pragma unroll
        for (int p = tid; p < BK * BN / 4; p += THREADS) {
            int r = p / (BN / 4);
            int cc = (p % (BN / 4)) * 4;
            float4 v = *(const float4*)&W[(size_t)(k0 + r) * N + bcol + cc];
            const float vv[4] = {v.x, v.y, v.z, v.w};
#pragma unroll
            for (int j = 0; j < 4; j++) {
                uint32_t big = f2tf32(vv[j]);
                float res = vv[j] - __uint_as_float(big);
                Ws[0][r * WS + cc + j] = __uint_as_float(big);
                Ws[1][r * WS + cc + j] = __uint_as_float(f2tf32(res));
            }
        }
        __syncthreads();

#pragma unroll
        for (int ks = 0; ks < BK / 8; ks++) {
            const int kb = ks * 8;
            uint32_t Ab[2][4], Ar[2][4];
#pragma unroll
            for (int mi = 0; mi < 2; mi++) {
                int r0 = wrb + mi * 16 + g;
                Ab[mi][0] = __float_as_uint(As[0][r0 * AS + kb + tg]);
                Ab[mi][1] = __float_as_uint(As[0][(r0 + 8) * AS + kb + tg]);
                Ab[mi][2] = __float_as_uint(As[0][r0 * AS + kb + tg + 4]);
                Ab[mi][3] = __float_as_uint(As[0][(r0 + 8) * AS + kb + tg + 4]);
                Ar[mi][0] = __float_as_uint(As[1][r0 * AS + kb + tg]);
                Ar[mi][1] = __float_as_uint(As[1][(r0 + 8) * AS + kb + tg]);
                Ar[mi][2] = __float_as_uint(As[1][r0 * AS + kb + tg + 4]);
                Ar[mi][3] = __float_as_uint(As[1][(r0 + 8) * AS + kb + tg + 4]);
            }
#pragma unroll
            for (int ni = 0; ni < NF; ni++) {
                int col = wcb + ni * 8 + g;
                uint32_t Bb0 = __float_as_uint(Ws[0][(kb + tg) * WS + col]);
                uint32_t Bb1 = __float_as_uint(Ws[0][(kb + tg + 4) * WS + col]);
                uint32_t Br0 = __float_as_uint(Ws[1][(kb + tg) * WS + col]);
                uint32_t Br1 = __float_as_uint(Ws[1][(kb + tg + 4) * WS + col]);
#pragma unroll
                for (int mi = 0; mi < 2; mi++) {
                    mma_tf32(c[mi][ni], Ab[mi], Bb0, Bb1);
                    mma_tf32(c[mi][ni], Ar[mi], Bb0, Bb1);
                    mma_tf32(c[mi][ni], Ab[mi], Br0, Br1);
                }
            }
        }
        __syncthreads();
    }

#pragma unroll
    for (int mi = 0; mi < 2; mi++) {
        int gr0 = brow + wrb + mi * 16 + g;
        int gr1 = gr0 + 8;
#pragma unroll
        for (int ni = 0; ni < NF; ni++) {
            int gc = bcol + wcb + ni * 8 + 2 * tg;
            if (gr0 < M)
                *(__half2*)&C[(size_t)gr0 * N + gc] =
                    __floats2half2_rn(c[mi][ni][0], c[mi][ni][1]);
            if (gr1 < M)
                *(__half2*)&C[(size_t)gr1 * N + gc] =
                    __floats2half2_rn(c[mi][ni][2], c[mi][ni][3]);
        }
    }
}

// ---------------- agg1: fp16 gather, relu, fp16 out (D=128) ----------------

__global__ void agg1_kernel(__half* __restrict__ out,
                            const __half* __restrict__ H,
                            const float* __restrict__ b, int n) {
    constexpr int D = 128;
    int warp = (blockIdx.x * blockDim.x + threadIdx.x) >> 5;
    int f = threadIdx.x & 31;
    int i = warp;                      // 1 node per warp
    if (i >= n) return;

    float di = g_dinv[i];
    float s2 = di * di;
    uint2 hp = *(const uint2*)&H[(size_t)i * D + 4 * f];
    float2 h01 = __half22float2(*(__half2*)&hp.x);
    float2 h23 = __half22float2(*(__half2*)&hp.y);
    float4 bb = ((const float4*)b)[f];
    float4 acc;
    acc.x = bb.x + s2 * h01.x;
    acc.y = bb.y + s2 * h01.y;
    acc.z = bb.z + s2 * h23.x;
    acc.w = bb.w + s2 * h23.y;

    int beg = g_offs[i], end = g_offs[i + 1];
#pragma unroll 8
    for (int e = beg; e < end; e++) {
        float2 p = __ldg(&g_csr[e]);
        int s = __float_as_int(p.x);
        float nrm = p.y;
        uint2 vp = *(const uint2*)&H[(size_t)s * D + 4 * f];
        float2 v01 = __half22float2(*(__half2*)&vp.x);
        float2 v23 = __half22float2(*(__half2*)&vp.y);
        acc.x += nrm * v01.x;
        acc.y += nrm * v01.y;
        acc.z += nrm * v23.x;
        acc.w += nrm * v23.y;
    }

    acc.x = fmaxf(acc.x, 0.0f);
    acc.y = fmaxf(acc.y, 0.0f);
    acc.z = fmaxf(acc.z, 0.0f);
    acc.w = fmaxf(acc.w, 0.0f);

    uint2 o;
    *(__half2*)&o.x = __floats2half2_rn(acc.x, acc.y);
    *(__half2*)&o.y = __floats2half2_rn(acc.z, acc.w);
    *(uint2*)&out[(size_t)i * D + 4 * f] = o;
}

// ------- agg2 + fused 64x16 GEMV: h2 = agg(H2)+b2; logits = h2 @ W3 --------

__global__ void agg2_gemv_kernel(float* __restrict__ outH3,   // n x 16
                                 const __half* __restrict__ H,
                                 const float* __restrict__ b2,
                                 const float* __restrict__ W3, int n) {
    __shared__ __align__(16) float W3s[64 * 16];
    {
        int t = threadIdx.x;
        if (t < 256) ((float4*)W3s)[t] = ((const float4*)W3)[t];
    }
    __syncthreads();

    constexpr int D = 64, LPN = 16, NPW = 2;
    int warp = (blockIdx.x * blockDim.x + threadIdx.x) >> 5;
    int lane = threadIdx.x & 31;
    int grp = lane >> 4;
    int f = lane & 15;
    int i = warp * NPW + grp;
    if (i >= n) return;

    float di = g_dinv[i];
    float s2 = di * di;
    uint2 hp = *(const uint2*)&H[(size_t)i * D + 4 * f];
    float2 h01 = __half22float2(*(__half2*)&hp.x);
    float2 h23 = __half22float2(*(__half2*)&hp.y);
    float4 bb = ((const float4*)b2)[f];
    float4 acc;
    acc.x = bb.x + s2 * h01.x;
    acc.y = bb.y + s2 * h01.y;
    acc.z = bb.z + s2 * h23.x;
    acc.w = bb.w + s2 * h23.y;

    int beg = g_offs[i], end = g_offs[i + 1];
#pragma unroll 4
    for (int e = beg; e < end; e++) {
        float2 p = __ldg(&g_csr[e]);
        int s = __float_as_int(p.x);
        float nrm = p.y;
        uint2 vp = *(const uint2*)&H[(size_t)s * D + 4 * f];
        float2 v01 = __half22float2(*(__half2*)&vp.x);
        float2 v23 = __half22float2(*(__half2*)&vp.y);
        acc.x += nrm * v01.x;
        acc.y += nrm * v01.y;
        acc.z += nrm * v23.x;
        acc.w += nrm * v23.y;
    }

    // GEMV: logit[f] = sum_j sum_k h2[4j+k] * W3[4j+k][f]
    float part = 0.0f;
#pragma unroll
    for (int j = 0; j < LPN; j++) {
        float ax = __shfl_sync(0xFFFFFFFFu, acc.x, j, 16);
        float ay = __shfl_sync(0xFFFFFFFFu, acc.y, j, 16);
        float az = __shfl_sync(0xFFFFFFFFu, acc.z, j, 16);
        float aw = __shfl_sync(0xFFFFFFFFu, acc.w, j, 16);
        part += ax * W3s[(4 * j + 0) * 16 + f];
        part += ay * W3s[(4 * j + 1) * 16 + f];
        part += az * W3s[(4 * j + 2) * 16 + f];
        part += aw * W3s[(4 * j + 3) * 16 + f];
    }
    outH3[(size_t)i * 16 + f] = part;
}

// ---------------- agg3: fp32 gather over logits + softmax (D=16) -----------

__global__ void agg3_kernel(float* __restrict__ out,
                            const float* __restrict__ H,
                            const float* __restrict__ b, int n) {
    constexpr int LPN = 4, NPW = 8;
    int warp = (blockIdx.x * blockDim.x + threadIdx.x) >> 5;
    int lane = threadIdx.x & 31;
    int grp = lane / LPN;
    int f = lane % LPN;
    int i = warp * NPW + grp;
    if (i >= n) return;

    float di = g_dinv[i];
    float s2 = di * di;
    float4 h = ((const float4*)H)[(size_t)i * LPN + f];
    float4 bb = ((const float4*)b)[f];
    float4 acc;
    acc.x = bb.x + s2 * h.x;
    acc.y = bb.y + s2 * h.y;
    acc.z = bb.z + s2 * h.z;
    acc.w = bb.w + s2 * h.w;

    int beg = g_offs[i], end = g_offs[i + 1];
#pragma unroll 4
    for (int e = beg; e < end; e++) {
        float2 p = __ldg(&g_csr[e]);
        int s = __float_as_int(p.x);
        float nrm = p.y;
        float4 v = ((const float4*)H)[(size_t)s * LPN + f];
        acc.x += nrm * v.x;
        acc.y += nrm * v.y;
        acc.z += nrm * v.z;
        acc.w += nrm * v.w;
    }

    float m = fmaxf(fmaxf(acc.x, acc.y), fmaxf(acc.z, acc.w));
#pragma unroll
    for (int o = 1; o < LPN; o <<= 1)
        m = fmaxf(m, __shfl_xor_sync(0xFFFFFFFFu, m, o, LPN));
    acc.x = __expf(acc.x - m);
    acc.y = __expf(acc.y - m);
    acc.z = __expf(acc.z - m);
    acc.w = __expf(acc.w - m);
    float s = acc.x + acc.y + acc.z + acc.w;
#pragma unroll
    for (int o = 1; o < LPN; o <<= 1)
        s += __shfl_xor_sync(0xFFFFFFFFu, s, o, LPN);
    float inv = 1.0f / s;
    acc.x *= inv;
    acc.y *= inv;
    acc.z *= inv;
    acc.w *= inv;

    ((float4*)out)[(size_t)i * LPN + f] = acc;
}

// ------------------------------- launch -----------------------------------

static cudaStream_t s_gemm = nullptr;
static cudaEvent_t  s_evFork = nullptr, s_evJoin = nullptr;

extern "C" void kernel_launch(void* const* d_in, const int* in_sizes, int n_in,
                              void* d_out, int out_size) {
    const float* x  = (const float*)d_in[0];
    const int*   ei = (const int*)d_in[1];   // int32 (JAX x64 disabled)
    const float* W1 = (const float*)d_in[2];
    const float* b1 = (const float*)d_in[3];
    const float* W2 = (const float*)d_in[4];
    const float* b2 = (const float*)d_in[5];
    const float* W3 = (const float*)d_in[6];
    const float* b3 = (const float*)d_in[7];

    const int n = in_sizes[0] / 128;
    const int E = in_sizes[1] / 2;
    const int* src = ei;
    const int* dst = ei + E;

    float* H3;
    __half *H16, *A16;
    cudaGetSymbolAddress((void**)&H16, g_H16);
    cudaGetSymbolAddress((void**)&A16, g_A16);
    cudaGetSymbolAddress((void**)&H3, g_H3);

    if (s_gemm == nullptr) {
        cudaStreamCreateWithFlags(&s_gemm, cudaStreamNonBlocking);
        cudaEventCreateWithFlags(&s_evFork, cudaEventDisableTiming);
        cudaEventCreateWithFlags(&s_evJoin, cudaEventDisableTiming);
    }

    const int T = 256;
    auto blocks = [&](long long work) { return (int)((work + T - 1) / T); };
    const int gy = (n + 127) / 128;

    // Fork: layer-1 GEMM (independent of CSR) on side stream.
    cudaEventRecord(s_evFork, 0);
    cudaStreamWaitEvent(s_gemm, s_evFork, 0);
    gemm_tf32_kernel<128, float>
        <<<dim3(1, gy), 256, 0, s_gemm>>>(x, W1, H16, n, 128, 128);
    cudaEventRecord(s_evJoin, s_gemm);

    // Fused CSR build (concurrent with GEMM1). g_deg zero at entry.
    prep_kernel<<<PREP_BLOCKS, PREP_THREADS>>>(src, dst, n, E);

    // Join: agg1 needs both CSR and H.
    cudaStreamWaitEvent(0, s_evJoin, 0);

    // ----- layer 1 aggregation (fp16 in/out, relu fused) -----
    agg1_kernel<<<blocks((long long)n * 32), T>>>(A16, H16, b1, n);

    // ----- layer 2: 128 -> 64 (tf32 TC, fp16 in -> fp16 H) -----
    gemm_tf32_kernel<64, __half>
        <<<dim3(1, gy), 256>>>(A16, W2, H16, n, 128, 64);

    // ----- layer 2 agg + fused layer-3 GEMV -> logits -----
    agg2_gemv_kernel<<<blocks((long long)n * 16), T>>>(H3, H16, b2, W3, n);

    // ----- layer 3 aggregation + softmax -> d_out -----
    agg3_kernel<<<blocks((long long)n * 4), T>>>((float*)d_out, H3, b3, n);
}

// round 14
// speedup vs baseline: 1.5455x; 1.4951x over previous
#include <cuda_runtime.h>
#include <cuda_fp16.h>
#include <cstdint>

// ---------------------------------------------------------------------------
// ExtendedGCN: 3-layer GCN (PyG GCNConv) + softmax.
//   Pull-based aggregation over per-call CSR-by-dst, packed (src, norm);
//   CSR via memset+deg+scan1+scan3+scatter (best-measured R11 chain).
//   Layers 1/2 GEMM: native fp16 HMMA (m16n8k16, fp32 accum), fp16 in/out.
//   Layer-3 GEMV (64x16) fused into agg2 epilogue; relu in agg1; softmax agg3.
//   CSR build overlapped with layer-1 GEMM on a second stream.
// edge_index is int32 on device (JAX x64 disabled).
// ---------------------------------------------------------------------------

#define NMAX 50000
#define EMAX 800000
#define SCAN_B 1024
#define NSCANB ((NMAX + SCAN_B - 1) / SCAN_B)

__device__ __half g_H16[(size_t)NMAX * 128];  // fp16 GEMM outputs (layers 1/2)
__device__ __half g_A16[(size_t)NMAX * 128];  // fp16 agg1 output (GEMM2 input)
__device__ float  g_H3[(size_t)NMAX * 16];    // fp32 layer-3 logits (pre-agg)
__device__ float  g_dinv[NMAX];
__device__ int    g_deg[NMAX];
__device__ int    g_offs[NMAX + 1];
__device__ int    g_cursor[NMAX];
__device__ float2 g_csr[EMAX];                // (src as int bits, norm)
__device__ int    g_bsum[NSCANB];

// ----------------------------- CSR build ----------------------------------

__global__ void deg_kernel(const int* __restrict__ dst, int E) {
    int e = blockIdx.x * blockDim.x + threadIdx.x;
    if (e < E) atomicAdd(&g_deg[dst[e]], 1);
}

__global__ void scan1_kernel(int n) {
    __shared__ int warp_tot[32];
    int tid = threadIdx.x;
    int lane = tid & 31;
    int warp = tid >> 5;
    int gid = blockIdx.x * SCAN_B + tid;
    int v = (gid < n) ? g_deg[gid] : 0;
    if (gid < n) g_dinv[gid] = rsqrtf((float)(v + 1));

    int inc = v;
#pragma unroll
    for (int o = 1; o < 32; o <<= 1) {
        int t = __shfl_up_sync(0xFFFFFFFFu, inc, o);
        if (lane >= o) inc += t;
    }
    if (lane == 31) warp_tot[warp] = inc;
    __syncthreads();
    if (warp == 0) {
        int w = warp_tot[lane];
        int wi = w;
#pragma unroll
        for (int o = 1; o < 32; o <<= 1) {
            int t = __shfl_up_sync(0xFFFFFFFFu, wi, o);
            if (lane >= o) wi += t;
        }
        warp_tot[lane] = wi - w;
        if (lane == 31) g_bsum[blockIdx.x] = wi;
    }
    __syncthreads();
    if (gid < n) g_offs[gid] = inc - v + warp_tot[warp];
}

__global__ void scan3_kernel(int n, int E) {
    __shared__ int pre;
    int tid = threadIdx.x;
    if (tid < 32) {
        int acc = 0;
        for (int j = tid; j < (int)blockIdx.x; j += 32) acc += g_bsum[j];
#pragma unroll
        for (int o = 16; o > 0; o >>= 1)
            acc += __shfl_xor_sync(0xFFFFFFFFu, acc, o);
        if (tid == 0) pre = acc;
    }
    __syncthreads();
    int gid = blockIdx.x * SCAN_B + tid;
    if (gid < n) {
        int o = g_offs[gid] + pre;
        g_offs[gid] = o;
        g_cursor[gid] = o;
    }
    if (gid == n) g_offs[n] = E;
}

__global__ void scatter_kernel(const int* __restrict__ src,
                               const int* __restrict__ dst, int E) {
    int e = blockIdx.x * blockDim.x + threadIdx.x;
    if (e < E) {
        int s = src[e], d = dst[e];
        int pos = atomicAdd(&g_cursor[d], 1);
        float nrm = g_dinv[s] * g_dinv[d];
        g_csr[pos] = make_float2(__int_as_float(s), nrm);
    }
}

// ------------------------- fp16 tensor GEMM --------------------------------
// C[M,N] = A[M,K] @ W[K,N], mma.m16n8k16.f32.f16.f16.f32, fp32 accumulate.
// BM=128, BK=32, 256 threads (8 warps as 4x2), warp tile 32 x (BN/2).
// A staged [BM][BK] halves (stride AS2=BK+8, conflict-free frag reads).
// W staged as k-pairs: Wp[kp][col] = half2(W[2kp][col], W[2kp+1][col]),
// stride WP=BN+8 half2 (≡8 mod 32 words -> conflict-free).

__device__ __forceinline__ void mma_f16(float* c, const uint32_t* a,
                                        uint32_t b0, uint32_t b1) {
    asm volatile(
        "mma.sync.aligned.m16n8k16.row.col.f32.f16.f16.f32 "
        "{%0,%1,%2,%3}, {%4,%5,%6,%7}, {%8,%9}, {%0,%1,%2,%3};\n"
        : "+f"(c[0]), "+f"(c[1]), "+f"(c[2]), "+f"(c[3])
        : "r"(a[0]), "r"(a[1]), "r"(a[2]), "r"(a[3]), "r"(b0), "r"(b1));
}

template <int BN, typename AT>
__global__ void gemm_f16_kernel(const AT* __restrict__ A,
                                const float* __restrict__ W,
                                __half* __restrict__ C, int M, int K, int N) {
    constexpr int BM = 128, BK = 32, THREADS = 256;
    constexpr int AS2 = BK + 8;                 // halves per A row (40)
    constexpr int WP = BN + 8;                  // half2 per Wp row
    constexpr int NF = BN / 16;                 // n8 frags per warp
    constexpr bool A_HALF = (sizeof(AT) == 2);

    __shared__ __align__(16) __half  As[BM * AS2];
    __shared__ __align__(16) __half2 Wp[(BK / 2) * WP];

    const int tid = threadIdx.x;
    const int lane = tid & 31;
    const int warp = tid >> 5;
    const int g = lane >> 2;
    const int tg = lane & 3;
    const int wrb = (warp & 3) * 32;
    const int wcb = (warp >> 2) * (BN / 2);
    const int brow = blockIdx.y * BM;
    const int bcol = blockIdx.x * BN;

    float c[2][NF][4];
#pragma unroll
    for (int mi = 0; mi < 2; mi++)
#pragma unroll
        for (int ni = 0; ni < NF; ni++)
#pragma unroll
            for (int j = 0; j < 4; j++) c[mi][ni][j] = 0.0f;

    for (int k0 = 0; k0 < K; k0 += BK) {
        // ---- stage A (BM x BK halves), packets of 4 elements ----
#pragma unroll
        for (int p = tid; p < BM * BK / 4; p += THREADS) {
            int r = p / (BK / 4);
            int c4 = (p % (BK / 4)) * 4;
            int gr = brow + r;
            uint2 pk = make_uint2(0u, 0u);      // 4 halves
            if (gr < M) {
                if (A_HALF) {
                    pk = *(const uint2*)&A[(size_t)gr * K + k0 + c4];
                } else {
                    float4 v = *(const float4*)&A[(size_t)gr * K + k0 + c4];
                    __half2 h01 = __floats2half2_rn(v.x, v.y);
                    __half2 h23 = __floats2half2_rn(v.z, v.w);
                    pk.x = *(uint32_t*)&h01;
                    pk.y = *(uint32_t*)&h23;
                }
            }
            *(uint2*)&As[r * AS2 + c4] = pk;
        }
        // ---- stage W as k-pairs ----
#pragma unroll
        for (int q = tid; q < (BK / 2) * BN; q += THREADS) {
            int kp = q / BN;
            int cc = q % BN;
            float w0 = W[(size_t)(k0 + 2 * kp) * N + bcol + cc];
            float w1 = W[(size_t)(k0 + 2 * kp + 1) * N + bcol + cc];
            Wp[kp * WP + cc] = __floats2half2_rn(w0, w1);
        }
        __syncthreads();

#pragma unroll
        for (int ks = 0; ks < BK / 16; ks++) {
            const int kh = ks * 16;             // half offset in As
            const int kp0 = ks * 8;             // pair offset in Wp
            uint32_t a[2][4];
#pragma unroll
            for (int mi = 0; mi < 2; mi++) {
                int r0 = wrb + mi * 16 + g;
                a[mi][0] = *(const uint32_t*)&As[r0 * AS2 + kh + 2 * tg];
                a[mi][1] = *(const uint32_t*)&As[(r0 + 8) * AS2 + kh + 2 * tg];
                a[mi][2] = *(const uint32_t*)&As[r0 * AS2 + kh + 2 * tg + 8];
                a[mi][3] = *(const uint32_t*)&As[(r0 + 8) * AS2 + kh + 2 * tg + 8];
            }
#pragma unroll
            for (int ni = 0; ni < NF; ni++) {
                int col = wcb + ni * 8 + g;
                uint32_t b0 = *(const uint32_t*)&Wp[(kp0 + tg) * WP + col];
                uint32_t b1 = *(const uint32_t*)&Wp[(kp0 + tg + 4) * WP + col];
#pragma unroll
                for (int mi = 0; mi < 2; mi++)
                    mma_f16(c[mi][ni], a[mi], b0, b1);
            }
        }
        __syncthreads();
    }

    // epilogue (m16n8 C layout: c0,c1 -> row g col 2tg; c2,c3 -> row g+8)
#pragma unroll
    for (int mi = 0; mi < 2; mi++) {
        int gr0 = brow + wrb + mi * 16 + g;
        int gr1 = gr0 + 8;
#pragma unroll
        for (int ni = 0; ni < NF; ni++) {
            int gc = bcol + wcb + ni * 8 + 2 * tg;
            if (gr0 < M)
                *(__half2*)&C[(size_t)gr0 * N + gc] =
                    __floats2half2_rn(c[mi][ni][0], c[mi][ni][1]);
            if (gr1 < M)
                *(__half2*)&C[(size_t)gr1 * N + gc] =
                    __floats2half2_rn(c[mi][ni][2], c[mi][ni][3]);
        }
    }
}

// ---------------- agg1: fp16 gather, relu, fp16 out (D=128) ----------------

__global__ void agg1_kernel(__half* __restrict__ out,
                            const __half* __restrict__ H,
                            const float* __restrict__ b, int n) {
    constexpr int D = 128;
    int warp = (blockIdx.x * blockDim.x + threadIdx.x) >> 5;
    int f = threadIdx.x & 31;
    int i = warp;
    if (i >= n) return;

    float di = g_dinv[i];
    float s2 = di * di;
    uint2 hp = *(const uint2*)&H[(size_t)i * D + 4 * f];
    float2 h01 = __half22float2(*(__half2*)&hp.x);
    float2 h23 = __half22float2(*(__half2*)&hp.y);
    float4 bb = ((const float4*)b)[f];
    float4 acc;
    acc.x = bb.x + s2 * h01.x;
    acc.y = bb.y + s2 * h01.y;
    acc.z = bb.z + s2 * h23.x;
    acc.w = bb.w + s2 * h23.y;

    int beg = g_offs[i], end = g_offs[i + 1];
#pragma unroll 8
    for (int e = beg; e < end; e++) {
        float2 p = __ldg(&g_csr[e]);
        int s = __float_as_int(p.x);
        float nrm = p.y;
        uint2 vp = *(const uint2*)&H[(size_t)s * D + 4 * f];
        float2 v01 = __half22float2(*(__half2*)&vp.x);
        float2 v23 = __half22float2(*(__half2*)&vp.y);
        acc.x += nrm * v01.x;
        acc.y += nrm * v01.y;
        acc.z += nrm * v23.x;
        acc.w += nrm * v23.y;
    }

    acc.x = fmaxf(acc.x, 0.0f);
    acc.y = fmaxf(acc.y, 0.0f);
    acc.z = fmaxf(acc.z, 0.0f);
    acc.w = fmaxf(acc.w, 0.0f);

    uint2 o;
    *(__half2*)&o.x = __floats2half2_rn(acc.x, acc.y);
    *(__half2*)&o.y = __floats2half2_rn(acc.z, acc.w);
    *(uint2*)&out[(size_t)i * D + 4 * f] = o;
}

// ------- agg2 + fused 64x16 GEMV: h2 = agg(H2)+b2; logits = h2 @ W3 --------

__global__ void agg2_gemv_kernel(float* __restrict__ outH3,
                                 const __half* __restrict__ H,
                                 const float* __restrict__ b2,
                                 const float* __restrict__ W3, int n) {
    __shared__ __align__(16) float W3s[64 * 16];
    {
        int t = threadIdx.x;
        if (t < 256) ((float4*)W3s)[t] = ((const float4*)W3)[t];
    }
    __syncthreads();

    constexpr int D = 64, LPN = 16, NPW = 2;
    int warp = (blockIdx.x * blockDim.x + threadIdx.x) >> 5;
    int lane = threadIdx.x & 31;
    int grp = lane >> 4;
    int f = lane & 15;
    int i = warp * NPW + grp;
    if (i >= n) return;

    float di = g_dinv[i];
    float s2 = di * di;
    uint2 hp = *(const uint2*)&H[(size_t)i * D + 4 * f];
    float2 h01 = __half22float2(*(__half2*)&hp.x);
    float2 h23 = __half22float2(*(__half2*)&hp.y);
    float4 bb = ((const float4*)b2)[f];
    float4 acc;
    acc.x = bb.x + s2 * h01.x;
    acc.y = bb.y + s2 * h01.y;
    acc.z = bb.z + s2 * h23.x;
    acc.w = bb.w + s2 * h23.y;

    int beg = g_offs[i], end = g_offs[i + 1];
#pragma unroll 4
    for (int e = beg; e < end; e++) {
        float2 p = __ldg(&g_csr[e]);
        int s = __float_as_int(p.x);
        float nrm = p.y;
        uint2 vp = *(const uint2*)&H[(size_t)s * D + 4 * f];
        float2 v01 = __half22float2(*(__half2*)&vp.x);
        float2 v23 = __half22float2(*(__half2*)&vp.y);
        acc.x += nrm * v01.x;
        acc.y += nrm * v01.y;
        acc.z += nrm * v23.x;
        acc.w += nrm * v23.y;
    }

    float part = 0.0f;
#pragma unroll
    for (int j = 0; j < LPN; j++) {
        float ax = __shfl_sync(0xFFFFFFFFu, acc.x, j, 16);
        float ay = __shfl_sync(0xFFFFFFFFu, acc.y, j, 16);
        float az = __shfl_sync(0xFFFFFFFFu, acc.z, j, 16);
        float aw = __shfl_sync(0xFFFFFFFFu, acc.w, j, 16);
        part += ax * W3s[(4 * j + 0) * 16 + f];
        part += ay * W3s[(4 * j + 1) * 16 + f];
        part += az * W3s[(4 * j + 2) * 16 + f];
        part += aw * W3s[(4 * j + 3) * 16 + f];
    }
    outH3[(size_t)i * 16 + f] = part;
}

// ---------------- agg3: fp32 gather over logits + softmax (D=16) -----------

__global__ void agg3_kernel(float* __restrict__ out,
                            const float* __restrict__ H,
                            const float* __restrict__ b, int n) {
    constexpr int LPN = 4, NPW = 8;
    int warp = (blockIdx.x * blockDim.x + threadIdx.x) >> 5;
    int lane = threadIdx.x & 31;
    int grp = lane / LPN;
    int f = lane % LPN;
    int i = warp * NPW + grp;
    if (i >= n) return;

    float di = g_dinv[i];
    float s2 = di * di;
    float4 h = ((const float4*)H)[(size_t)i * LPN + f];
    float4 bb = ((const float4*)b)[f];
    float4 acc;
    acc.x = bb.x + s2 * h.x;
    acc.y = bb.y + s2 * h.y;
    acc.z = bb.z + s2 * h.z;
    acc.w = bb.w + s2 * h.w;

    int beg = g_offs[i], end = g_offs[i + 1];
#pragma unroll 4
    for (int e = beg; e < end; e++) {
        float2 p = __ldg(&g_csr[e]);
        int s = __float_as_int(p.x);
        float nrm = p.y;
        float4 v = ((const float4*)H)[(size_t)s * LPN + f];
        acc.x += nrm * v.x;
        acc.y += nrm * v.y;
        acc.z += nrm * v.z;
        acc.w += nrm * v.w;
    }

    float m = fmaxf(fmaxf(acc.x, acc.y), fmaxf(acc.z, acc.w));
#pragma unroll
    for (int o = 1; o < LPN; o <<= 1)
        m = fmaxf(m, __shfl_xor_sync(0xFFFFFFFFu, m, o, LPN));
    acc.x = __expf(acc.x - m);
    acc.y = __expf(acc.y - m);
    acc.z = __expf(acc.z - m);
    acc.w = __expf(acc.w - m);
    float s = acc.x + acc.y + acc.z + acc.w;
#pragma unroll
    for (int o = 1; o < LPN; o <<= 1)
        s += __shfl_xor_sync(0xFFFFFFFFu, s, o, LPN);
    float inv = 1.0f / s;
    acc.x *= inv;
    acc.y *= inv;
    acc.z *= inv;
    acc.w *= inv;

    ((float4*)out)[(size_t)i * LPN + f] = acc;
}

// ------------------------------- launch -----------------------------------

static cudaStream_t s_gemm = nullptr;
static cudaEvent_t  s_evFork = nullptr, s_evJoin = nullptr;

extern "C" void kernel_launch(void* const* d_in, const int* in_sizes, int n_in,
                              void* d_out, int out_size) {
    const float* x  = (const float*)d_in[0];
    const int*   ei = (const int*)d_in[1];   // int32 (JAX x64 disabled)
    const float* W1 = (const float*)d_in[2];
    const float* b1 = (const float*)d_in[3];
    const float* W2 = (const float*)d_in[4];
    const float* b2 = (const float*)d_in[5];
    const float* W3 = (const float*)d_in[6];
    const float* b3 = (const float*)d_in[7];

    const int n = in_sizes[0] / 128;
    const int E = in_sizes[1] / 2;
    const int* src = ei;
    const int* dst = ei + E;

    float* H3;
    __half *H16, *A16;
    int* degp;
    cudaGetSymbolAddress((void**)&H16, g_H16);
    cudaGetSymbolAddress((void**)&A16, g_A16);
    cudaGetSymbolAddress((void**)&H3, g_H3);
    cudaGetSymbolAddress((void**)&degp, g_deg);

    if (s_gemm == nullptr) {
        cudaStreamCreateWithFlags(&s_gemm, cudaStreamNonBlocking);
        cudaEventCreateWithFlags(&s_evFork, cudaEventDisableTiming);
        cudaEventCreateWithFlags(&s_evJoin, cudaEventDisableTiming);
    }

    const int T = 256;
    auto blocks = [&](long long work) { return (int)((work + T - 1) / T); };
    const int nScanBlocks = (n + SCAN_B - 1) / SCAN_B;
    const int gy = (n + 127) / 128;

    // Fork: layer-1 GEMM (independent of CSR) on side stream.
    cudaEventRecord(s_evFork, 0);
    cudaStreamWaitEvent(s_gemm, s_evFork, 0);
    gemm_f16_kernel<128, float>
        <<<dim3(1, gy), 256, 0, s_gemm>>>(x, W1, H16, n, 128, 128);
    cudaEventRecord(s_evJoin, s_gemm);

    // CSR build on main stream (concurrent with GEMM1).
    cudaMemsetAsync(degp, 0, (size_t)n * sizeof(int), 0);
    deg_kernel<<<blocks(E), T>>>(dst, E);
    scan1_kernel<<<nScanBlocks, SCAN_B>>>(n);
    scan3_kernel<<<nScanBlocks, SCAN_B>>>(n, E);
    scatter_kernel<<<blocks(E), T>>>(src, dst, E);

    // Join: agg1 needs both CSR and H.
    cudaStreamWaitEvent(0, s_evJoin, 0);

    // ----- layer 1 aggregation (fp16 in/out, relu fused) -----
    agg1_kernel<<<blocks((long long)n * 32), T>>>(A16, H16, b1, n);

    // ----- layer 2: 128 -> 64 (fp16 HMMA) -----
    gemm_f16_kernel<64, __half>
        <<<dim3(1, gy), 256>>>(A16, W2, H16, n, 128, 64);

    // ----- layer 2 agg + fused layer-3 GEMV -> logits -----
    agg2_gemv_kernel<<<blocks((long long)n * 16), T>>>(H3, H16, b2, W3, n);

    // ----- layer 3 aggregation + softmax -> d_out -----
    agg3_kernel<<<blocks((long long)n * 4), T>>>((float*)d_out, H3, b3, n);
}

// round 15
// speedup vs baseline: 1.5684x; 1.0149x over previous
#include <cuda_runtime.h>
#include <cuda_fp16.h>
#include <cstdint>

// ---------------------------------------------------------------------------
// ExtendedGCN: 3-layer GCN (PyG GCNConv) + softmax.
//   Pull-based aggregation over per-call CSR-by-dst, packed (src, norm).
//   Prep = 3 launches: deg (atomics) -> scan (49-block, one grid barrier,
//   self-zeroes deg -> no memset) -> scatter (cursor atomics).
//   Layers 1/2 GEMM: native fp16 HMMA (m16n8k16, fp32 accum), fp16 in/out.
//   Layer-3 GEMV (64x16) fused into agg2 epilogue; relu in agg1; softmax agg3.
//   Prep overlapped with layer-1 GEMM on a second stream.
// edge_index is int32 on device (JAX x64 disabled).
// g_deg invariant: zero at call entry (BSS zero-init + scan re-zeroes).
// ---------------------------------------------------------------------------

#define NMAX 50000
#define EMAX 800000
#define SCAN_B 1024
#define NSCANB ((NMAX + SCAN_B - 1) / SCAN_B)   // 49

__device__ __half g_H16[(size_t)NMAX * 128];  // fp16 GEMM outputs (layers 1/2)
__device__ __half g_A16[(size_t)NMAX * 128];  // fp16 agg1 output (GEMM2 input)
__device__ float  g_H3[(size_t)NMAX * 16];    // fp32 layer-3 logits (pre-agg)
__device__ float  g_dinv[NMAX];
__device__ int    g_deg[NMAX];                // zero at entry, re-zeroed by scan
__device__ int    g_offs[NMAX + 1];
__device__ int    g_cursor[NMAX];
__device__ float2 g_csr[EMAX];                // (src as int bits, norm)
__device__ int    g_bsum[NSCANB];

// -------- software grid barrier (sense-reversing; replay-safe state) -------

__device__ volatile unsigned g_bar_gen = 0;
__device__ unsigned g_bar_cnt = 0;

__device__ __forceinline__ void grid_barrier() {
    __syncthreads();
    if (threadIdx.x == 0) {
        __threadfence();
        unsigned my = g_bar_gen;
        if (atomicAdd(&g_bar_cnt, 1) == gridDim.x - 1) {
            atomicExch(&g_bar_cnt, 0);
            __threadfence();
            g_bar_gen = my + 1;
        } else {
            while (g_bar_gen == my) {}
        }
    }
    __syncthreads();
}

// ----------------------------- CSR build ----------------------------------

__global__ void deg_kernel(const int* __restrict__ dst, int E) {
    int e = blockIdx.x * blockDim.x + threadIdx.x;
    if (e < E) atomicAdd(&g_deg[dst[e]], 1);
}

// 49 blocks x 1024: tile scan -> totals -> grid barrier -> prefix; writes
// offs/cursor/dinv; self-zeroes deg.  Leaves 99 SMs free for GEMM1 overlap.
__global__ void __launch_bounds__(SCAN_B, 1)
scan_kernel(int n, int E) {
    __shared__ int warp_tot[32];
    const int tid = threadIdx.x;
    const int lane = tid & 31;
    const int warp = tid >> 5;
    const int bid = blockIdx.x;
    const int idx = bid * SCAN_B + tid;

    int v = (idx < n) ? g_deg[idx] : 0;
    if (idx < n) {
        g_dinv[idx] = rsqrtf((float)(v + 1));
        g_deg[idx] = 0;                       // self-clean for next call
    }

    int inc = v;
#pragma unroll
    for (int o = 1; o < 32; o <<= 1) {
        int x = __shfl_up_sync(0xFFFFFFFFu, inc, o);
        if (lane >= o) inc += x;
    }
    if (lane == 31) warp_tot[warp] = inc;
    __syncthreads();
    if (warp == 0) {
        int w = warp_tot[lane];
        int wi = w;
#pragma unroll
        for (int o = 1; o < 32; o <<= 1) {
            int x = __shfl_up_sync(0xFFFFFFFFu, wi, o);
            if (lane >= o) wi += x;
        }
        warp_tot[lane] = wi - w;
        if (lane == 31) g_bsum[bid] = wi;
    }
    __syncthreads();
    int excl = inc - v + warp_tot[warp];

    grid_barrier();                            // all tile totals published

    int pre = 0;
    for (int j = 0; j < bid; j++) pre += g_bsum[j];   // <=48 L1 broadcast hits
    if (idx < n) {
        int o = excl + pre;
        g_offs[idx] = o;
        g_cursor[idx] = o;
    }
    if (idx == n) g_offs[n] = E;
}

__global__ void scatter_kernel(const int* __restrict__ src,
                               const int* __restrict__ dst, int E) {
    int e = blockIdx.x * blockDim.x + threadIdx.x;
    if (e < E) {
        int s = src[e], d = dst[e];
        int pos = atomicAdd(&g_cursor[d], 1);
        float nrm = g_dinv[s] * g_dinv[d];
        g_csr[pos] = make_float2(__int_as_float(s), nrm);
    }
}

// ------------------------- fp16 tensor GEMM --------------------------------
// C[M,N] = A[M,K] @ W[K,N], mma.m16n8k16.f32.f16.f16.f32, fp32 accumulate.

__device__ __forceinline__ void mma_f16(float* c, const uint32_t* a,
                                        uint32_t b0, uint32_t b1) {
    asm volatile(
        "mma.sync.aligned.m16n8k16.row.col.f32.f16.f16.f32 "
        "{%0,%1,%2,%3}, {%4,%5,%6,%7}, {%8,%9}, {%0,%1,%2,%3};\n"
        : "+f"(c[0]), "+f"(c[1]), "+f"(c[2]), "+f"(c[3])
        : "r"(a[0]), "r"(a[1]), "r"(a[2]), "r"(a[3]), "r"(b0), "r"(b1));
}

template <int BN, typename AT>
__global__ void gemm_f16_kernel(const AT* __restrict__ A,
                                const float* __restrict__ W,
                                __half* __restrict__ C, int M, int K, int N) {
    constexpr int BM = 128, BK = 32, THREADS = 256;
    constexpr int AS2 = BK + 8;
    constexpr int WP = BN + 8;
    constexpr int NF = BN / 16;
    constexpr bool A_HALF = (sizeof(AT) == 2);

    __shared__ __align__(16) __half  As[BM * AS2];
    __shared__ __align__(16) __half2 Wp[(BK / 2) * WP];

    const int tid = threadIdx.x;
    const int lane = tid & 31;
    const int warp = tid >> 5;
    const int g = lane >> 2;
    const int tg = lane & 3;
    const int wrb = (warp & 3) * 32;
    const int wcb = (warp >> 2) * (BN / 2);
    const int brow = blockIdx.y * BM;
    const int bcol = blockIdx.x * BN;

    float c[2][NF][4];
#pragma unroll
    for (int mi = 0; mi < 2; mi++)
#pragma unroll
        for (int ni = 0; ni < NF; ni++)
#pragma unroll
            for (int j = 0; j < 4; j++) c[mi][ni][j] = 0.0f;

    for (int k0 = 0; k0 < K; k0 += BK) {
#pragma unroll
        for (int p = tid; p < BM * BK / 4; p += THREADS) {
            int r = p / (BK / 4);
            int c4 = (p % (BK / 4)) * 4;
            int gr = brow + r;
            uint2 pk = make_uint2(0u, 0u);
            if (gr < M) {
                if (A_HALF) {
                    pk = *(const uint2*)&A[(size_t)gr * K + k0 + c4];
                } else {
                    float4 v = *(const float4*)&A[(size_t)gr * K + k0 + c4];
                    __half2 h01 = __floats2half2_rn(v.x, v.y);
                    __half2 h23 = __floats2half2_rn(v.z, v.w);
                    pk.x = *(uint32_t*)&h01;
                    pk.y = *(uint32_t*)&h23;
                }
            }
            *(uint2*)&As[r * AS2 + c4] = pk;
        }
#pragma unroll
        for (int q = tid; q < (BK / 2) * BN; q += THREADS) {
            int kp = q / BN;
            int cc = q % BN;
            float w0 = W[(size_t)(k0 + 2 * kp) * N + bcol + cc];
            float w1 = W[(size_t)(k0 + 2 * kp + 1) * N + bcol + cc];
            Wp[kp * WP + cc] = __floats2half2_rn(w0, w1);
        }
        __syncthreads();

#pragma unroll
        for (int ks = 0; ks < BK / 16; ks++) {
            const int kh = ks * 16;
            const int kp0 = ks * 8;
            uint32_t a[2][4];
#pragma unroll
            for (int mi = 0; mi < 2; mi++) {
                int r0 = wrb + mi * 16 + g;
                a[mi][0] = *(const uint32_t*)&As[r0 * AS2 + kh + 2 * tg];
                a[mi][1] = *(const uint32_t*)&As[(r0 + 8) * AS2 + kh + 2 * tg];
                a[mi][2] = *(const uint32_t*)&As[r0 * AS2 + kh + 2 * tg + 8];
                a[mi][3] = *(const uint32_t*)&As[(r0 + 8) * AS2 + kh + 2 * tg + 8];
            }
#pragma unroll
            for (int ni = 0; ni < NF; ni++) {
                int col = wcb + ni * 8 + g;
                uint32_t b0 = *(const uint32_t*)&Wp[(kp0 + tg) * WP + col];
                uint32_t b1 = *(const uint32_t*)&Wp[(kp0 + tg + 4) * WP + col];
#pragma unroll
                for (int mi = 0; mi < 2; mi++)
                    mma_f16(c[mi][ni], a[mi], b0, b1);
            }
        }
        __syncthreads();
    }

#pragma unroll
    for (int mi = 0; mi < 2; mi++) {
        int gr0 = brow + wrb + mi * 16 + g;
        int gr1 = gr0 + 8;
#pragma unroll
        for (int ni = 0; ni < NF; ni++) {
            int gc = bcol + wcb + ni * 8 + 2 * tg;
            if (gr0 < M)
                *(__half2*)&C[(size_t)gr0 * N + gc] =
                    __floats2half2_rn(c[mi][ni][0], c[mi][ni][1]);
            if (gr1 < M)
                *(__half2*)&C[(size_t)gr1 * N + gc] =
                    __floats2half2_rn(c[mi][ni][2], c[mi][ni][3]);
        }
    }
}

// ---------------- agg1: fp16 gather, relu, fp16 out (D=128) ----------------

__global__ void agg1_kernel(__half* __restrict__ out,
                            const __half* __restrict__ H,
                            const float* __restrict__ b, int n) {
    constexpr int D = 128;
    int warp = (blockIdx.x * blockDim.x + threadIdx.x) >> 5;
    int f = threadIdx.x & 31;
    int i = warp;
    if (i >= n) return;

    float di = g_dinv[i];
    float s2 = di * di;
    uint2 hp = *(const uint2*)&H[(size_t)i * D + 4 * f];
    float2 h01 = __half22float2(*(__half2*)&hp.x);
    float2 h23 = __half22float2(*(__half2*)&hp.y);
    float4 bb = ((const float4*)b)[f];
    float4 acc;
    acc.x = bb.x + s2 * h01.x;
    acc.y = bb.y + s2 * h01.y;
    acc.z = bb.z + s2 * h23.x;
    acc.w = bb.w + s2 * h23.y;

    int beg = g_offs[i], end = g_offs[i + 1];
#pragma unroll 8
    for (int e = beg; e < end; e++) {
        float2 p = __ldg(&g_csr[e]);
        int s = __float_as_int(p.x);
        float nrm = p.y;
        uint2 vp = *(const uint2*)&H[(size_t)s * D + 4 * f];
        float2 v01 = __half22float2(*(__half2*)&vp.x);
        float2 v23 = __half22float2(*(__half2*)&vp.y);
        acc.x += nrm * v01.x;
        acc.y += nrm * v01.y;
        acc.z += nrm * v23.x;
        acc.w += nrm * v23.y;
    }

    acc.x = fmaxf(acc.x, 0.0f);
    acc.y = fmaxf(acc.y, 0.0f);
    acc.z = fmaxf(acc.z, 0.0f);
    acc.w = fmaxf(acc.w, 0.0f);

    uint2 o;
    *(__half2*)&o.x = __floats2half2_rn(acc.x, acc.y);
    *(__half2*)&o.y = __floats2half2_rn(acc.z, acc.w);
    *(uint2*)&out[(size_t)i * D + 4 * f] = o;
}

// ------- agg2 + fused 64x16 GEMV: h2 = agg(H2)+b2; logits = h2 @ W3 --------

__global__ void agg2_gemv_kernel(float* __restrict__ outH3,
                                 const __half* __restrict__ H,
                                 const float* __restrict__ b2,
                                 const float* __restrict__ W3, int n) {
    __shared__ __align__(16) float W3s[64 * 16];
    {
        int t = threadIdx.x;
        if (t < 256) ((float4*)W3s)[t] = ((const float4*)W3)[t];
    }
    __syncthreads();

    constexpr int D = 64, LPN = 16, NPW = 2;
    int warp = (blockIdx.x * blockDim.x + threadIdx.x) >> 5;
    int lane = threadIdx.x & 31;
    int grp = lane >> 4;
    int f = lane & 15;
    int i = warp * NPW + grp;
    if (i >= n) return;

    float di = g_dinv[i];
    float s2 = di * di;
    uint2 hp = *(const uint2*)&H[(size_t)i * D + 4 * f];
    float2 h01 = __half22float2(*(__half2*)&hp.x);
    float2 h23 = __half22float2(*(__half2*)&hp.y);
    float4 bb = ((const float4*)b2)[f];
    float4 acc;
    acc.x = bb.x + s2 * h01.x;
    acc.y = bb.y + s2 * h01.y;
    acc.z = bb.z + s2 * h23.x;
    acc.w = bb.w + s2 * h23.y;

    int beg = g_offs[i], end = g_offs[i + 1];
#pragma unroll 4
    for (int e = beg; e < end; e++) {
        float2 p = __ldg(&g_csr[e]);
        int s = __float_as_int(p.x);
        float nrm = p.y;
        uint2 vp = *(const uint2*)&H[(size_t)s * D + 4 * f];
        float2 v01 = __half22float2(*(__half2*)&vp.x);
        float2 v23 = __half22float2(*(__half2*)&vp.y);
        acc.x += nrm * v01.x;
        acc.y += nrm * v01.y;
        acc.z += nrm * v23.x;
        acc.w += nrm * v23.y;
    }

    float part = 0.0f;
#pragma unroll
    for (int j = 0; j < LPN; j++) {
        float ax = __shfl_sync(0xFFFFFFFFu, acc.x, j, 16);
        float ay = __shfl_sync(0xFFFFFFFFu, acc.y, j, 16);
        float az = __shfl_sync(0xFFFFFFFFu, acc.z, j, 16);
        float aw = __shfl_sync(0xFFFFFFFFu, acc.w, j, 16);
        part += ax * W3s[(4 * j + 0) * 16 + f];
        part += ay * W3s[(4 * j + 1) * 16 + f];
        part += az * W3s[(4 * j + 2) * 16 + f];
        part += aw * W3s[(4 * j + 3) * 16 + f];
    }
    outH3[(size_t)i * 16 + f] = part;
}

// ---------------- agg3: fp32 gather over logits + softmax (D=16) -----------

__global__ void agg3_kernel(float* __restrict__ out,
                            const float* __restrict__ H,
                            const float* __restrict__ b, int n) {
    constexpr int LPN = 4, NPW = 8;
    int warp = (blockIdx.x * blockDim.x + threadIdx.x) >> 5;
    int lane = threadIdx.x & 31;
    int grp = lane / LPN;
    int f = lane % LPN;
    int i = warp * NPW + grp;
    if (i >= n) return;

    float di = g_dinv[i];
    float s2 = di * di;
    float4 h = ((const float4*)H)[(size_t)i * LPN + f];
    float4 bb = ((const float4*)b)[f];
    float4 acc;
    acc.x = bb.x + s2 * h.x;
    acc.y = bb.y + s2 * h.y;
    acc.z = bb.z + s2 * h.z;
    acc.w = bb.w + s2 * h.w;

    int beg = g_offs[i], end = g_offs[i + 1];
#pragma unroll 4
    for (int e = beg; e < end; e++) {
        float2 p = __ldg(&g_csr[e]);
        int s = __float_as_int(p.x);
        float nrm = p.y;
        float4 v = ((const float4*)H)[(size_t)s * LPN + f];
        acc.x += nrm * v.x;
        acc.y += nrm * v.y;
        acc.z += nrm * v.z;
        acc.w += nrm * v.w;
    }

    float m = fmaxf(fmaxf(acc.x, acc.y), fmaxf(acc.z, acc.w));
#pragma unroll
    for (int o = 1; o < LPN; o <<= 1)
        m = fmaxf(m, __shfl_xor_sync(0xFFFFFFFFu, m, o, LPN));
    acc.x = __expf(acc.x - m);
    acc.y = __expf(acc.y - m);
    acc.z = __expf(acc.z - m);
    acc.w = __expf(acc.w - m);
    float s = acc.x + acc.y + acc.z + acc.w;
#pragma unroll
    for (int o = 1; o < LPN; o <<= 1)
        s += __shfl_xor_sync(0xFFFFFFFFu, s, o, LPN);
    float inv = 1.0f / s;
    acc.x *= inv;
    acc.y *= inv;
    acc.z *= inv;
    acc.w *= inv;

    ((float4*)out)[(size_t)i * LPN + f] = acc;
}

// ------------------------------- launch -----------------------------------

static cudaStream_t s_gemm = nullptr;
static cudaEvent_t  s_evFork = nullptr, s_evJoin = nullptr;

extern "C" void kernel_launch(void* const* d_in, const int* in_sizes, int n_in,
                              void* d_out, int out_size) {
    const float* x  = (const float*)d_in[0];
    const int*   ei = (const int*)d_in[1];   // int32 (JAX x64 disabled)
    const float* W1 = (const float*)d_in[2];
    const float* b1 = (const float*)d_in[3];
    const float* W2 = (const float*)d_in[4];
    const float* b2 = (const float*)d_in[5];
    const float* W3 = (const float*)d_in[6];
    const float* b3 = (const float*)d_in[7];

    const int n = in_sizes[0] / 128;
    const int E = in_sizes[1] / 2;
    const int* src = ei;
    const int* dst = ei + E;

    float* H3;
    __half *H16, *A16;
    cudaGetSymbolAddress((void**)&H16, g_H16);
    cudaGetSymbolAddress((void**)&A16, g_A16);
    cudaGetSymbolAddress((void**)&H3, g_H3);

    if (s_gemm == nullptr) {
        cudaStreamCreateWithFlags(&s_gemm, cudaStreamNonBlocking);
        cudaEventCreateWithFlags(&s_evFork, cudaEventDisableTiming);
        cudaEventCreateWithFlags(&s_evJoin, cudaEventDisableTiming);
    }

    const int T = 256;
    auto blocks = [&](long long work) { return (int)((work + T - 1) / T); };
    const int nScanBlocks = (n + SCAN_B - 1) / SCAN_B;
    const int gy = (n + 127) / 128;

    // Fork: layer-1 GEMM (independent of CSR) on side stream.
    cudaEventRecord(s_evFork, 0);
    cudaStreamWaitEvent(s_gemm, s_evFork, 0);
    gemm_f16_kernel<128, float>
        <<<dim3(1, gy), 256, 0, s_gemm>>>(x, W1, H16, n, 128, 128);
    cudaEventRecord(s_evJoin, s_gemm);

    // CSR build on main stream (3 launches; g_deg zero at entry).
    deg_kernel<<<blocks(E), T>>>(dst, E);
    scan_kernel<<<nScanBlocks, SCAN_B>>>(n, E);
    scatter_kernel<<<blocks(E), T>>>(src, dst, E);

    // Join: agg1 needs both CSR and H.
    cudaStreamWaitEvent(0, s_evJoin, 0);

    // ----- layer 1 aggregation (fp16 in/out, relu fused) -----
    agg1_kernel<<<blocks((long long)n * 32), T>>>(A16, H16, b1, n);

    // ----- layer 2: 128 -> 64 (fp16 HMMA) -----
    gemm_f16_kernel<64, __half>
        <<<dim3(1, gy), 256>>>(A16, W2, H16, n, 128, 64);

    // ----- layer 2 agg + fused layer-3 GEMV -> logits -----
    agg2_gemv_kernel<<<blocks((long long)n * 16), T>>>(H3, H16, b2, W3, n);

    // ----- layer 3 aggregation + softmax -> d_out -----
    agg3_kernel<<<blocks((long long)n * 4), T>>>((float*)d_out, H3, b3, n);
}